// round 6
// baseline (speedup 1.0000x reference)
#include <cuda_runtime.h>
#include <cuda_bf16.h>
#include <stdint.h>
#include <math.h>

// ---------------- model dims ----------------
#define B_ 4
#define L_ 1024
#define D_IN 128
#define D_MODEL 512
#define N_LAYERS 2
#define N_CLASSES 3
#define D_INNER 1024          // 2*D_MODEL
#define D_STATE 64
#define D_CONV 2
#define DT_RANK 32
#define ML (B_ * L_)          // 4096 rows

// ---------------- scratch (device globals; no allocation) ----------------
__device__ float g_h[ML * D_MODEL];
__device__ float g_xz[ML * 2 * D_INNER];
__device__ float g_xc[ML * D_INNER];
__device__ float g_dbc[ML * (DT_RANK + 2 * D_STATE)];
__device__ float g_dt[ML * D_INNER];

// bf16 hi/lo planes
__device__ __nv_bfloat16 g_hh[ML * D_MODEL],  g_hl[ML * D_MODEL];    // h planes
__device__ __nv_bfloat16 g_xch[ML * D_INNER], g_xcl[ML * D_INNER];   // xc planes (also x for embed)
__device__ __nv_bfloat16 g_dbch[ML * 160],    g_dbcl[ML * 160];      // dbc planes
__device__ __nv_bfloat16 g_yh[ML * D_INNER],  g_yl[ML * D_INNER];    // y planes
__device__ __nv_bfloat16 g_wh[2 * D_INNER * D_MODEL], g_wl[2 * D_INNER * D_MODEL]; // weight planes

__device__ __forceinline__ float softplus_f(float v) {
    return (v > 20.f) ? v : log1pf(__expf(v));
}
__device__ __forceinline__ void split2(float e0, float e1, unsigned int& hi, unsigned int& lo) {
    __nv_bfloat162 h = __floats2bfloat162_rn(e0, e1);
    float r0 = e0 - __bfloat162float(h.x);
    float r1 = e1 - __bfloat162float(h.y);
    __nv_bfloat162 l = __floats2bfloat162_rn(r0, r1);
    hi = *reinterpret_cast<unsigned int*>(&h);
    lo = *reinterpret_cast<unsigned int*>(&l);
}
__device__ __forceinline__ void mma_bf16(float* c, const unsigned int* a, const unsigned int* b) {
    asm volatile(
        "mma.sync.aligned.m16n8k16.row.col.f32.bf16.bf16.f32 "
        "{%0,%1,%2,%3}, {%4,%5,%6,%7}, {%8,%9}, {%0,%1,%2,%3};\n"
        : "+f"(c[0]), "+f"(c[1]), "+f"(c[2]), "+f"(c[3])
        : "r"(a[0]), "r"(a[1]), "r"(a[2]), "r"(a[3]),
          "r"(b[0]), "r"(b[1]));
}
__device__ __forceinline__ void cp16(unsigned int smem, const void* gmem, int srcbytes) {
    asm volatile("cp.async.cg.shared.global [%0], [%1], 16, %2;\n"
                 :: "r"(smem), "l"(gmem), "r"(srcbytes));
}

// ---------------- splitter: packed fp32 -> bf16 hi/lo planes ----------------
__global__ void splitf(const float* __restrict__ src,
                       __nv_bfloat16* __restrict__ hi,
                       __nv_bfloat16* __restrict__ lo, int n)
{
    int i = (blockIdx.x * blockDim.x + threadIdx.x) * 4;
    if (i >= n) return;
    float4 v = *(const float4*)(src + i);
    unsigned int h0, l0, h1, l1;
    split2(v.x, v.y, h0, l0);
    split2(v.z, v.w, h1, l1);
    *(uint2*)(hi + i) = make_uint2(h0, h1);
    *(uint2*)(lo + i) = make_uint2(l0, l1);
}

// ---------------- split-bf16 (3-term) GEMM, pre-split planes ----------------
// C = A(M,K; alda) @ W(N,K)^T (+bias)(+act), optional split C planes out.
// CTA 128x128, BK=32, 256 threads = 8 warps of 64x32, cp.async double buffer.
// SMEM pair-word rows stride 20 -> conflict-free fragment LDS.
#define SKW 20

__global__ __launch_bounds__(256, 2)
void gemm_pre(const __nv_bfloat16* __restrict__ Ah, const __nv_bfloat16* __restrict__ Al, int alda,
              const __nv_bfloat16* __restrict__ Wh, const __nv_bfloat16* __restrict__ Wl,
              const float* __restrict__ bias, float* __restrict__ C,
              __nv_bfloat16* __restrict__ Ch, __nv_bfloat16* __restrict__ Cl,
              int M, int N, int K, int act)
{
    __shared__ unsigned int SH[2][4][128][SKW];   // planes: 0=Ah 1=Al 2=Wh 3=Wl

    const int tid = threadIdx.x;
    const int lane = tid & 31, w = tid >> 5;
    const int g = lane >> 2, l4 = lane & 3;
    const int wm = (w >> 2) * 64, wn = (w & 3) * 32;
    const int m0 = blockIdx.y * 128, n0 = blockIdx.x * 128;

    // loader: rows lrow and lrow+64, 16B chunk lchunk (8 bf16)
    const int lrow = tid >> 2;
    const int lchunk = tid & 3;
    const int ce = lchunk * 8;   // element offset within BK

    const __nv_bfloat16* Ah0 = Ah + (long)(m0 + lrow) * alda + ce;
    const __nv_bfloat16* Ah1 = Ah0 + (long)64 * alda;
    const __nv_bfloat16* Al0 = Al + (long)(m0 + lrow) * alda + ce;
    const __nv_bfloat16* Al1 = Al0 + (long)64 * alda;
    const int wr0 = n0 + lrow, wr1 = wr0 + 64;
    const __nv_bfloat16* Wh0 = Wh + (long)(wr0 < N ? wr0 : 0) * K + ce;
    const __nv_bfloat16* Wh1 = Wh + (long)(wr1 < N ? wr1 : 0) * K + ce;
    const __nv_bfloat16* Wl0 = Wl + (long)(wr0 < N ? wr0 : 0) * K + ce;
    const __nv_bfloat16* Wl1 = Wl + (long)(wr1 < N ? wr1 : 0) * K + ce;
    const int wb0 = (wr0 < N) ? 16 : 0;
    const int wb1 = (wr1 < N) ? 16 : 0;

    const unsigned int sb = (unsigned int)__cvta_generic_to_shared(SH);
    const unsigned int so = (unsigned int)(lrow * (SKW * 4) + lchunk * 16);
    const unsigned int PL = 128 * SKW * 4;       // plane stride bytes
    const unsigned int ST = 4 * PL;              // stage stride bytes
    const unsigned int R64 = 64 * SKW * 4;

    float acc[4][4][4];
#pragma unroll
    for (int i = 0; i < 4; i++)
#pragma unroll
        for (int j = 0; j < 4; j++)
#pragma unroll
            for (int e = 0; e < 4; e++) acc[i][j][e] = 0.f;

    const int niter = K / 32;

    // prologue: stage 0
    {
        const unsigned int b0 = sb + so;
        cp16(b0,                 Ah0, 16);
        cp16(b0 + R64,           Ah1, 16);
        cp16(b0 + PL,            Al0, 16);
        cp16(b0 + PL + R64,      Al1, 16);
        cp16(b0 + 2 * PL,        Wh0, wb0);
        cp16(b0 + 2 * PL + R64,  Wh1, wb1);
        cp16(b0 + 3 * PL,        Wl0, wb0);
        cp16(b0 + 3 * PL + R64,  Wl1, wb1);
        asm volatile("cp.async.commit_group;\n");
    }

    for (int it = 0; it < niter; it++) {
        const int s = it & 1;
        if (it + 1 < niter) {
            const int k0 = (it + 1) * 32;
            const unsigned int b = sb + (s ^ 1) * ST + so;
            cp16(b,                Ah0 + k0, 16);
            cp16(b + R64,          Ah1 + k0, 16);
            cp16(b + PL,           Al0 + k0, 16);
            cp16(b + PL + R64,     Al1 + k0, 16);
            cp16(b + 2 * PL,       Wh0 + k0, wb0);
            cp16(b + 2 * PL + R64, Wh1 + k0, wb1);
            cp16(b + 3 * PL,       Wl0 + k0, wb0);
            cp16(b + 3 * PL + R64, Wl1 + k0, wb1);
            asm volatile("cp.async.commit_group;\n");
            asm volatile("cp.async.wait_group 1;\n");
        } else {
            asm volatile("cp.async.wait_group 0;\n");
        }
        __syncthreads();

#pragma unroll
        for (int ks = 0; ks < 2; ks++) {
            const int kb = ks * 8 + l4;
            unsigned int bh[4][2], bl[4][2];
#pragma unroll
            for (int j = 0; j < 4; j++) {
                const int r = wn + 8 * j + g;
                bh[j][0] = SH[s][2][r][kb];
                bh[j][1] = SH[s][2][r][kb + 4];
                bl[j][0] = SH[s][3][r][kb];
                bl[j][1] = SH[s][3][r][kb + 4];
            }
#pragma unroll
            for (int i = 0; i < 4; i++) {
                const int r0 = wm + 16 * i + g, r1 = r0 + 8;
                unsigned int ah[4], al[4];
                ah[0] = SH[s][0][r0][kb];     ah[1] = SH[s][0][r1][kb];
                ah[2] = SH[s][0][r0][kb + 4]; ah[3] = SH[s][0][r1][kb + 4];
                al[0] = SH[s][1][r0][kb];     al[1] = SH[s][1][r1][kb];
                al[2] = SH[s][1][r0][kb + 4]; al[3] = SH[s][1][r1][kb + 4];
#pragma unroll
                for (int j = 0; j < 4; j++) mma_bf16(acc[i][j], ah, bh[j]);
#pragma unroll
                for (int j = 0; j < 4; j++) mma_bf16(acc[i][j], ah, bl[j]);
#pragma unroll
                for (int j = 0; j < 4; j++) mma_bf16(acc[i][j], al, bh[j]);
            }
        }
        __syncthreads();
    }

    // epilogue
#pragma unroll
    for (int i = 0; i < 4; i++) {
        const int mr0 = m0 + wm + 16 * i + g;
        const int mr1 = mr0 + 8;
#pragma unroll
        for (int j = 0; j < 4; j++) {
            const int n = n0 + wn + 8 * j + 2 * l4;
            if (n < N) {
                float b0 = 0.f, b1 = 0.f;
                if (bias) { b0 = bias[n]; b1 = bias[n + 1]; }
                float v0 = acc[i][j][0] + b0, v1 = acc[i][j][1] + b1;
                float v2 = acc[i][j][2] + b0, v3 = acc[i][j][3] + b1;
                if (act == 1) {
                    v0 = softplus_f(v0); v1 = softplus_f(v1);
                    v2 = softplus_f(v2); v3 = softplus_f(v3);
                }
                *(float2*)(C + (long)mr0 * N + n) = make_float2(v0, v1);
                *(float2*)(C + (long)mr1 * N + n) = make_float2(v2, v3);
                if (Ch) {
                    unsigned int ph, pl;
                    split2(v0, v1, ph, pl);
                    *(unsigned int*)(Ch + (long)mr0 * N + n) = ph;
                    *(unsigned int*)(Cl + (long)mr0 * N + n) = pl;
                    split2(v2, v3, ph, pl);
                    *(unsigned int*)(Ch + (long)mr1 * N + n) = ph;
                    *(unsigned int*)(Cl + (long)mr1 * N + n) = pl;
                }
            }
        }
    }
}

// ---------------- conv (D_CONV=2) + silu, writes fp32 + split planes ----------
__global__ void conv_silu_kernel(const float* __restrict__ xz,
                                 const float* __restrict__ cw,
                                 const float* __restrict__ cb,
                                 float* __restrict__ xc,
                                 __nv_bfloat16* __restrict__ xch,
                                 __nv_bfloat16* __restrict__ xcl)
{
    int idx = blockIdx.x * blockDim.x + threadIdx.x;
    if (idx >= ML * D_INNER) return;
    int d = idx & (D_INNER - 1);
    int row = idx >> 10;
    int tt = row & (L_ - 1);
    float cur = xz[(long)row * (2 * D_INNER) + d];
    float prev = (tt > 0) ? xz[(long)(row - 1) * (2 * D_INNER) + d] : 0.f;
    float v = prev * cw[d * 2 + 0] + cur * cw[d * 2 + 1] + cb[d];
    float sv = v / (1.f + __expf(-v));
    xc[idx] = sv;
    __nv_bfloat16 h = __float2bfloat16_rn(sv);
    xch[idx] = h;
    xcl[idx] = __float2bfloat16_rn(sv - __bfloat162float(h));
}

// ---------------- selective scan: one warp per (b, d); writes y planes -------
__global__ __launch_bounds__(128)
void scan_kernel(const float* __restrict__ dt, const float* __restrict__ xc,
                 const float* __restrict__ dbc, const float* __restrict__ xz,
                 const float* __restrict__ A_log, const float* __restrict__ Dp,
                 __nv_bfloat16* __restrict__ yh, __nv_bfloat16* __restrict__ yl)
{
    const int gw = (blockIdx.x * blockDim.x + threadIdx.x) >> 5;
    const int lane = threadIdx.x & 31;
    const int b = gw >> 10;
    const int d = gw & (D_INNER - 1);

    const float A0 = -__expf(A_log[d * D_STATE + 2 * lane]);
    const float A1 = -__expf(A_log[d * D_STATE + 2 * lane + 1]);
    const float Dd = Dp[d];

    const float* dtp = dt + (long)b * L_ * D_INNER + d;
    const float* xp  = xc + (long)b * L_ * D_INNER + d;
    const float* bcp = dbc + (long)b * L_ * 160 + DT_RANK + 2 * lane;
    const float* zp  = xz + (long)b * L_ * (2 * D_INNER) + D_INNER + d;
    __nv_bfloat16* yph = yh + (long)b * L_ * D_INNER + d;
    __nv_bfloat16* ypl = yl + (long)b * L_ * D_INNER + d;

    float h0 = 0.f, h1 = 0.f;
    for (int t = 0; t < L_; t++) {
        const float dtv = dtp[t * D_INNER];
        const float xv  = xp[t * D_INNER];
        const float2 Bv = *(const float2*)(bcp + t * 160);
        const float2 Cv = *(const float2*)(bcp + t * 160 + D_STATE);
        const float u = dtv * xv;
        h0 = h0 * __expf(dtv * A0) + u * Bv.x;
        h1 = h1 * __expf(dtv * A1) + u * Bv.y;
        float p = h0 * Cv.x + h1 * Cv.y;
#pragma unroll
        for (int o = 16; o; o >>= 1) p += __shfl_xor_sync(0xffffffffu, p, o);
        if (lane == 0) {
            const float zv = zp[t * (2 * D_INNER)];
            const float yv = (p + xv * Dd) * (zv / (1.f + __expf(-zv)));
            __nv_bfloat16 hh = __float2bfloat16_rn(yv);
            yph[t * D_INNER] = hh;
            ypl[t * D_INNER] = __float2bfloat16_rn(yv - __bfloat162float(hh));
        }
    }
}

// ---------------- final FC ----------------
__global__ void fc_kernel(const float* __restrict__ h, const float* __restrict__ fc_w,
                          const float* __restrict__ fc_b, float* __restrict__ out)
{
    const int w = threadIdx.x >> 5;
    const int lane = threadIdx.x & 31;
    if (w >= B_ * N_CLASSES) return;
    const int b = w / N_CLASSES, c = w % N_CLASSES;
    const float* hp = h + (long)(b * L_ + (L_ - 1)) * D_MODEL;
    float s = 0.f;
    for (int k = lane; k < D_MODEL; k += 32) s += hp[k] * fc_w[c * D_MODEL + k];
#pragma unroll
    for (int o = 16; o; o >>= 1) s += __shfl_xor_sync(0xffffffffu, s, o);
    if (lane == 0) out[b * N_CLASSES + c] = s + fc_b[c];
}

// ---------------- launch ----------------
extern "C" void kernel_launch(void* const* d_in, const int* in_sizes, int n_in,
                              void* d_out, int out_size)
{
    const float* x        = (const float*)d_in[0];
    const float* exp_w    = (const float*)d_in[1];
    const float* exp_b    = (const float*)d_in[2];
    const float* in_w     = (const float*)d_in[3];
    const float* conv_w   = (const float*)d_in[4];
    const float* conv_b   = (const float*)d_in[5];
    const float* xproj_w  = (const float*)d_in[6];
    const float* dtproj_w = (const float*)d_in[7];
    const float* dtproj_b = (const float*)d_in[8];
    const float* A_log    = (const float*)d_in[9];
    const float* Dp       = (const float*)d_in[10];
    const float* out_w    = (const float*)d_in[11];
    const float* fc_w     = (const float*)d_in[12];
    const float* fc_b     = (const float*)d_in[13];
    float* out = (float*)d_out;

    float *ph, *pxz, *pxc, *pdbc, *pdt;
    __nv_bfloat16 *phh, *phl, *pxch, *pxcl, *pdbch, *pdbcl, *pyh, *pyl, *pwh, *pwl;
    cudaGetSymbolAddress((void**)&ph,    g_h);
    cudaGetSymbolAddress((void**)&pxz,   g_xz);
    cudaGetSymbolAddress((void**)&pxc,   g_xc);
    cudaGetSymbolAddress((void**)&pdbc,  g_dbc);
    cudaGetSymbolAddress((void**)&pdt,   g_dt);
    cudaGetSymbolAddress((void**)&phh,   g_hh);
    cudaGetSymbolAddress((void**)&phl,   g_hl);
    cudaGetSymbolAddress((void**)&pxch,  g_xch);
    cudaGetSymbolAddress((void**)&pxcl,  g_xcl);
    cudaGetSymbolAddress((void**)&pdbch, g_dbch);
    cudaGetSymbolAddress((void**)&pdbcl, g_dbcl);
    cudaGetSymbolAddress((void**)&pyh,   g_yh);
    cudaGetSymbolAddress((void**)&pyl,   g_yl);
    cudaGetSymbolAddress((void**)&pwh,   g_wh);
    cudaGetSymbolAddress((void**)&pwl,   g_wl);

    // embed: h = x @ exp_w^T + exp_b   (4096 x 512, K=128)
    splitf<<<(ML * D_IN / 4 + 255) / 256, 256>>>(x, pxch, pxcl, ML * D_IN);
    splitf<<<(D_MODEL * D_IN / 4 + 255) / 256, 256>>>(exp_w, pwh, pwl, D_MODEL * D_IN);
    gemm_pre<<<dim3(D_MODEL / 128, ML / 128), 256>>>(pxch, pxcl, D_IN, pwh, pwl,
                                                     exp_b, ph, phh, phl,
                                                     ML, D_MODEL, D_IN, 0);

    for (int l = 0; l < N_LAYERS; l++) {
        const float* in_w_l   = in_w     + (long)l * 2 * D_INNER * D_MODEL;
        const float* conv_w_l = conv_w   + (long)l * D_INNER * D_CONV;
        const float* conv_b_l = conv_b   + (long)l * D_INNER;
        const float* xproj_l  = xproj_w  + (long)l * 160 * D_INNER;
        const float* dtw_l    = dtproj_w + (long)l * D_INNER * DT_RANK;
        const float* dtb_l    = dtproj_b + (long)l * D_INNER;
        const float* Alog_l   = A_log    + (long)l * D_INNER * D_STATE;
        const float* Dp_l     = Dp       + (long)l * D_INNER;
        const float* out_w_l  = out_w    + (long)l * D_MODEL * D_INNER;

        // xz = h @ in_w^T   (4096 x 2048, K=512)
        splitf<<<(2 * D_INNER * D_MODEL / 4 + 255) / 256, 256>>>(in_w_l, pwh, pwl,
                                                                 2 * D_INNER * D_MODEL);
        gemm_pre<<<dim3(2 * D_INNER / 128, ML / 128), 256>>>(phh, phl, D_MODEL, pwh, pwl,
                                                             nullptr, pxz, nullptr, nullptr,
                                                             ML, 2 * D_INNER, D_MODEL, 0);
        // conv + silu (-> fp32 + planes)
        conv_silu_kernel<<<(ML * D_INNER + 255) / 256, 256>>>(pxz, conv_w_l, conv_b_l,
                                                              pxc, pxch, pxcl);
        // dbc = xc @ xproj^T  (4096 x 160, K=1024), planes out for dt GEMM
        splitf<<<(160 * D_INNER / 4 + 255) / 256, 256>>>(xproj_l, pwh, pwl, 160 * D_INNER);
        gemm_pre<<<dim3(2, ML / 128), 256>>>(pxch, pxcl, D_INNER, pwh, pwl,
                                             nullptr, pdbc, pdbch, pdbcl,
                                             ML, 160, D_INNER, 0);
        // dt = softplus(dbc[:, :32] @ dtproj^T + b)  (4096 x 1024, K=32, alda=160)
        splitf<<<(D_INNER * DT_RANK / 4 + 255) / 256, 256>>>(dtw_l, pwh, pwl, D_INNER * DT_RANK);
        gemm_pre<<<dim3(D_INNER / 128, ML / 128), 256>>>(pdbch, pdbcl, 160, pwh, pwl,
                                                         dtb_l, pdt, nullptr, nullptr,
                                                         ML, D_INNER, DT_RANK, 1);
        // selective scan + Dp skip + silu(z) gating -> y planes
        scan_kernel<<<(B_ * D_INNER) / 4, 128>>>(pdt, pxc, pdbc, pxz, Alog_l, Dp_l, pyh, pyl);
        // h = y @ out_w^T  (4096 x 512, K=1024), planes out for next layer
        splitf<<<(D_MODEL * D_INNER / 4 + 255) / 256, 256>>>(out_w_l, pwh, pwl,
                                                             D_MODEL * D_INNER);
        gemm_pre<<<dim3(D_MODEL / 128, ML / 128), 256>>>(pyh, pyl, D_INNER, pwh, pwl,
                                                         nullptr, ph, phh, phl,
                                                         ML, D_MODEL, D_INNER, 0);
    }

    fc_kernel<<<1, 384>>>(ph, fc_w, fc_b, out);
}